// round 1
// baseline (speedup 1.0000x reference)
#include <cuda_runtime.h>
#include <math.h>

#define VOC   50257
#define EMB   128
#define N_MEM 8192
#define T_Q   50
#define T_M   50
#define N_HOPS 3

// ---------------- scratch (device globals; no allocation allowed) ----------------
__device__ float g_min [N_MEM * EMB];   // memory_in
__device__ float g_mout[N_MEM * EMB];   // memory_out
__device__ float g_u[EMB];
__device__ float g_scores[N_MEM];
__device__ int   g_smax[N_HOPS];
__device__ float g_denom[N_HOPS];
__device__ float g_wsum[N_HOPS * EMB];
__device__ int   g_lmax;
__device__ float g_lsum;

// ordered-int encoding for float atomicMax
__device__ __forceinline__ int f2oi(float f) {
    int i = __float_as_int(f);
    return (i >= 0) ? i : (i ^ 0x7FFFFFFF);
}
__device__ __forceinline__ float oi2f(int i) {
    return __int_as_float((i >= 0) ? i : (i ^ 0x7FFFFFFF));
}

// ---------------- init: reset reduction scratch ----------------
__global__ void k_init() {
    int t = threadIdx.x;
    if (t < N_HOPS) { g_smax[t] = f2oi(-INFINITY); g_denom[t] = 0.f; }
    if (t == N_HOPS) { g_lmax = f2oi(-INFINITY); g_lsum = 0.f; }
    if (t < N_HOPS * EMB) g_wsum[t] = 0.f;
}

// ---------------- memory build: warp per memory row, float4 lanes ----------------
__global__ void k_mem(const int* __restrict__ story,
                      const float* __restrict__ Wa, const float* __restrict__ Wc,
                      const float* __restrict__ TA, const float* __restrict__ TC) {
    int gw   = (blockIdx.x * blockDim.x + threadIdx.x) >> 5;   // global warp = memory idx
    int lane = threadIdx.x & 31;
    if (gw >= N_MEM) return;

    const float4* wa4 = (const float4*)Wa;
    const float4* wc4 = (const float4*)Wc;
    float4 ain  = ((const float4*)TA)[gw * 32 + lane];
    float4 aout = ((const float4*)TC)[gw * 32 + lane];
    const int* s = story + gw * T_M;

#pragma unroll 10
    for (int t = 0; t < T_M; t++) {
        int idx = __ldg(s + t);                      // uniform per-warp, L1 broadcast
        float4 a = wa4[(long)idx * 32 + lane];
        float4 c = wc4[(long)idx * 32 + lane];
        ain.x += a.x;  ain.y += a.y;  ain.z += a.z;  ain.w += a.w;
        aout.x += c.x; aout.y += c.y; aout.z += c.z; aout.w += c.w;
    }
    ((float4*)g_min )[gw * 32 + lane] = ain;
    ((float4*)g_mout)[gw * 32 + lane] = aout;
}

// ---------------- u0 = sum_t Wb[query[t]] ----------------
__global__ void k_u0(const int* __restrict__ q, const float* __restrict__ Wb) {
    int e = threadIdx.x;
    float a = 0.f;
#pragma unroll 10
    for (int t = 0; t < T_Q; t++) a += Wb[(long)__ldg(q + t) * EMB + e];
    g_u[e] = a;
}

// ---------------- hop pass 1: scores + global max ----------------
__global__ void k_scores(int hop) {
    __shared__ float4 su4[32];
    __shared__ float smax[8];
    int tid = threadIdx.x, lane = tid & 31, wid = tid >> 5;
    if (tid < 32) su4[tid] = ((const float4*)g_u)[tid];
    __syncthreads();
    float4 uu = su4[lane];

    int gw = (blockIdx.x * blockDim.x + tid) >> 5;
    int nw = (gridDim.x * blockDim.x) >> 5;
    float lmax = -INFINITY;
    for (int n = gw; n < N_MEM; n += nw) {
        float4 m = ((const float4*)(g_min + n * EMB))[lane];
        float p = m.x * uu.x + m.y * uu.y + m.z * uu.z + m.w * uu.w;
#pragma unroll
        for (int o = 16; o; o >>= 1) p += __shfl_xor_sync(0xFFFFFFFFu, p, o);
        if (lane == 0) g_scores[n] = p;
        lmax = fmaxf(lmax, p);
    }
    if (lane == 0) smax[wid] = lmax;
    __syncthreads();
    if (tid == 0) {
        float m = smax[0];
        for (int i = 1; i < (int)(blockDim.x >> 5); i++) m = fmaxf(m, smax[i]);
        atomicMax(&g_smax[hop], f2oi(m));
    }
}

// ---------------- hop pass 2: exp weights, denom, weighted sum ----------------
__global__ void k_weighted(int hop) {
    __shared__ float swsum[EMB];
    int tid = threadIdx.x, lane = tid & 31;
    if (tid < EMB) swsum[tid] = 0.f;
    __syncthreads();

    float mx = oi2f(g_smax[hop]);
    int gw = (blockIdx.x * blockDim.x + tid) >> 5;
    int nw = (gridDim.x * blockDim.x) >> 5;
    float4 acc = make_float4(0.f, 0.f, 0.f, 0.f);
    float den = 0.f;
    for (int n = gw; n < N_MEM; n += nw) {
        float w = __expf(g_scores[n] - mx);        // same value on all lanes
        den += w;
        float4 m = ((const float4*)(g_mout + n * EMB))[lane];
        acc.x += w * m.x; acc.y += w * m.y; acc.z += w * m.z; acc.w += w * m.w;
    }
    atomicAdd(&swsum[lane * 4 + 0], acc.x);
    atomicAdd(&swsum[lane * 4 + 1], acc.y);
    atomicAdd(&swsum[lane * 4 + 2], acc.z);
    atomicAdd(&swsum[lane * 4 + 3], acc.w);
    if (lane == 0) atomicAdd(&g_denom[hop], den);
    __syncthreads();
    if (tid < EMB) atomicAdd(&g_wsum[hop * EMB + tid], swsum[tid]);
}

// ---------------- hop pass 3: gated update of u ----------------
__global__ void k_update(int hop,
                         const float* __restrict__ Wt_w, const float* __restrict__ Wt_b,
                         const float* __restrict__ H_w,  const float* __restrict__ H_b) {
    __shared__ float su[EMB], swo[EMB];
    int e = threadIdx.x;
    su[e]  = g_u[e];
    swo[e] = g_wsum[hop * EMB + e] / g_denom[hop];
    __syncthreads();

    float dt = 0.f, dh = 0.f;
    const float* wr = Wt_w + e * EMB;
    const float* hr = H_w  + e * EMB;
#pragma unroll 8
    for (int k = 0; k < EMB; k++) {
        dt += wr[k] * su[k];
        dh += hr[k] * swo[k];
    }
    float t = 1.f / (1.f + expf(-(dt + Wt_b[e])));
    float h = dh + H_b[e];
    g_u[e] = su[e] * (1.f - t) + h * t;
}

// ---------------- final logits + max ----------------
__global__ void k_logits(const float* __restrict__ wout, float* __restrict__ out) {
    __shared__ float4 su4[32];
    __shared__ float smax[8];
    int tid = threadIdx.x, lane = tid & 31, wid = tid >> 5;
    if (tid < 32) su4[tid] = ((const float4*)g_u)[tid];
    __syncthreads();
    float4 uu = su4[lane];

    int gw = (blockIdx.x * blockDim.x + tid) >> 5;
    int nw = (gridDim.x * blockDim.x) >> 5;
    float lmax = -INFINITY;
    for (int v = gw; v < VOC; v += nw) {
        float4 m = ((const float4*)(wout + (long)v * EMB))[lane];
        float p = m.x * uu.x + m.y * uu.y + m.z * uu.z + m.w * uu.w;
#pragma unroll
        for (int o = 16; o; o >>= 1) p += __shfl_xor_sync(0xFFFFFFFFu, p, o);
        if (lane == 0) out[v] = p;
        lmax = fmaxf(lmax, p);
    }
    if (lane == 0) smax[wid] = lmax;
    __syncthreads();
    if (tid == 0) {
        float m = smax[0];
        for (int i = 1; i < (int)(blockDim.x >> 5); i++) m = fmaxf(m, smax[i]);
        atomicMax(&g_lmax, f2oi(m));
    }
}

// ---------------- log-softmax denom ----------------
__global__ void k_lsum(const float* __restrict__ out) {
    __shared__ float sred[256];
    float mx = oi2f(g_lmax);
    float s = 0.f;
    for (int v = blockIdx.x * blockDim.x + threadIdx.x; v < VOC; v += gridDim.x * blockDim.x)
        s += __expf(out[v] - mx);
    sred[threadIdx.x] = s;
    __syncthreads();
    for (int o = blockDim.x >> 1; o; o >>= 1) {
        if (threadIdx.x < o) sred[threadIdx.x] += sred[threadIdx.x + o];
        __syncthreads();
    }
    if (threadIdx.x == 0) atomicAdd(&g_lsum, sred[0]);
}

// ---------------- normalize ----------------
__global__ void k_norm(float* __restrict__ out) {
    float c = oi2f(g_lmax) + logf(g_lsum);
    for (int v = blockIdx.x * blockDim.x + threadIdx.x; v < VOC; v += gridDim.x * blockDim.x)
        out[v] -= c;
}

// ---------------- launch ----------------
extern "C" void kernel_launch(void* const* d_in, const int* in_sizes, int n_in,
                              void* d_out, int out_size) {
    const int*   query = (const int*)  d_in[0];
    const int*   story = (const int*)  d_in[1];
    const float* Wa    = (const float*)d_in[2];
    const float* Wc    = (const float*)d_in[3];
    const float* Wb    = (const float*)d_in[4];
    const float* Wt_w  = (const float*)d_in[5];
    const float* Wt_b  = (const float*)d_in[6];
    const float* H_w   = (const float*)d_in[7];
    const float* H_b   = (const float*)d_in[8];
    const float* wout  = (const float*)d_in[9];
    const float* TA    = (const float*)d_in[10];
    const float* TC    = (const float*)d_in[11];
    float* out = (float*)d_out;

    k_init<<<1, 512>>>();
    k_mem<<<(N_MEM * 32 + 127) / 128, 128>>>(story, Wa, Wc, TA, TC);
    k_u0<<<1, EMB>>>(query, Wb);

    for (int h = 0; h < N_HOPS; h++) {
        k_scores  <<<128, 256>>>(h);
        k_weighted<<<128, 256>>>(h);
        k_update  <<<1, EMB>>>(h, Wt_w, Wt_b, H_w, H_b);
    }

    k_logits<<<384, 256>>>(wout, out);
    k_lsum  <<<128, 256>>>(out);
    k_norm  <<<128, 256>>>(out);
}